// round 7
// baseline (speedup 1.0000x reference)
#include <cuda_runtime.h>
#include <cstdint>

#define N_AGENTS 8192

__global__ void rollout_policy_kernel(const float* __restrict__ x,
                                      const float* __restrict__ u,
                                      float* __restrict__ out)
{
    const int gtid = blockIdx.x * blockDim.x + threadIdx.x;
    const int agent = gtid >> 5;           // one warp per agent
    const int lane = threadIdx.x & 31;
    if (agent >= N_AGENTS) return;

    // x is (2N, 3) row-major: agents rows [0,N), goals rows [N,2N); cols 0,1 used.
    const float ax = x[3 * agent];
    const float ay = x[3 * agent + 1];
    const float* gbase = x + 3 * N_AGENTS;

    float best = __int_as_float(0x7f800000);   // +inf
    int   bi   = 0;

    // Ascending goal order per lane: strict < keeps the lane's first minimum.
    #pragma unroll 4
    for (int g = lane; g < N_AGENTS; g += 32) {
        float gx = __ldg(gbase + 3 * g);
        float gy = __ldg(gbase + 3 * g + 1);
        float d  = fabsf(ax - gx) + fabsf(ay - gy);
        if (d < best) { best = d; bi = g; }
    }

    // Warp reduction: lexicographic (dist, idx) min == first-occurrence argmin.
    const unsigned mask = 0xffffffffu;
    #pragma unroll
    for (int off = 16; off; off >>= 1) {
        float od = __shfl_xor_sync(mask, best, off);
        int   oi = __shfl_xor_sync(mask, bi,   off);
        if (od < best || (od == best && oi < bi)) { best = od; bi = oi; }
    }

    if (lane == 0) {
        float gx = __ldg(gbase + 3 * bi);
        float gy = __ldg(gbase + 3 * bi + 1);
        float dx = gx - ax;
        float dy = gy - ay;

        // probs = [dx>0, dx<0, dy>0, dy<0, (dx==0)&(dy==0)]; cdf = cumsum
        float c0 = (dx > 0.0f) ? 1.0f : 0.0f;
        float c1 = c0 + ((dx < 0.0f) ? 1.0f : 0.0f);
        float c2 = c1 + ((dy > 0.0f) ? 1.0f : 0.0f);
        float c3 = c2 + ((dy < 0.0f) ? 1.0f : 0.0f);
        float c4 = c3 + ((dx == 0.0f && dy == 0.0f) ? 1.0f : 0.0f);

        float t = u[agent] * c4;

        // argmax(cdf >= t) = first index whose cdf >= t (u==0 -> 0, matches jnp)
        int act = 4;
        if      (c0 >= t) act = 0;
        else if (c1 >= t) act = 1;
        else if (c2 >= t) act = 2;
        else if (c3 >= t) act = 3;

        out[agent] = (float)act;           // OUTPUT AS FLOAT32 (dtype-mismatch fix)
    }
}

extern "C" void kernel_launch(void* const* d_in, const int* in_sizes, int n_in,
                              void* d_out, int out_size)
{
    // Size-driven binding (in_sizes are element counts): x = 6*N, u = N.
    const float* x = nullptr;
    const float* u = nullptr;
    for (int i = 0; i < n_in; i++) {
        if (in_sizes[i] == 6 * N_AGENTS)      x = (const float*)d_in[i];
        else if (in_sizes[i] == N_AGENTS)     u = (const float*)d_in[i];
    }
    if (!x) x = (const float*)d_in[0];
    if (!u) u = (const float*)d_in[n_in > 1 ? 1 : 0];

    float* out = (float*)d_out;

    const int threads = 256;                              // 8 warps = 8 agents/block
    const int blocks  = (N_AGENTS * 32) / threads;        // 1024
    rollout_policy_kernel<<<blocks, threads>>>(x, u, out);
    (void)out_size;
}